// round 5
// baseline (speedup 1.0000x reference)
#include <cuda_runtime.h>
#include <stdint.h>

#define NFRAMES   256
#define VOX       32768
#define VOX4      (VOX / 4)          // 8192 float4 per channel per frame
#define KCAP      512
#define MAXEV     100
#define NT        256
#define BPF       8                  // blocks per frame
#define GRID      (NFRAMES * BPF)    // 2048
#define SLOTS     (VOX4 / BPF)       // 1024 float4 slots per block
#define HASH_SZ   1024
#define HASH_MASK 1023
#define HEMPTY    0xFFFFFFFFu
#define NBMAX     8
#define NB_OVF    0x80

#define ST_UNDEC 0
#define ST_KEPT  1
#define ST_SUPP  2

__device__ unsigned long long g_keys[NFRAMES * KCAP];
__device__ int                g_count[NFRAMES];
__device__ int                g_done[NFRAMES];

__global__ __launch_bounds__(NT)
void event_filter_fused(const float* __restrict__ in, float* __restrict__ out)
{
    const int frame = blockIdx.x >> 3;
    const int part  = blockIdx.x & 7;
    const int tid   = threadIdx.x;
    const int lane  = tid & 31;
    const unsigned FULL = 0xFFFFFFFFu;

    const float4* in4  = (const float4*)in;
    float4*       out4 = (float4*)out;
    const int base4 = frame << 14;               // frame start, float4 units (2*VOX4)

    // ================= Phase 1: stream 1/8 frame — zero output + compact =================
    {
        const float4 z4 = make_float4(0.f, 0.f, 0.f, 0.f);
        const int off0 = part * SLOTS + tid;
        #pragma unroll
        for (int k = 0; k < 4; k++) {
            const int off = off0 + k * NT;
            out4[base4 + off]        = z4;
            out4[base4 + VOX4 + off] = z4;

            float4 v = in4[base4 + off];
            unsigned m0 = __ballot_sync(FULL, v.x > 0.0f);
            unsigned m1 = __ballot_sync(FULL, v.y > 0.0f);
            unsigned m2 = __ballot_sync(FULL, v.z > 0.0f);
            unsigned m3 = __ballot_sync(FULL, v.w > 0.0f);
            if ((m0 | m1 | m2 | m3) == 0) continue;

            int tot = __popc(m0) + __popc(m1) + __popc(m2) + __popc(m3);
            int base;
            if (lane == 0) base = atomicAdd(&g_count[frame], tot);
            base = __shfl_sync(FULL, base, 0);

            const unsigned lt = (1u << lane) - 1u;
            int pre = __popc(m0 & lt) + __popc(m1 & lt) + __popc(m2 & lt) + __popc(m3 & lt);
            const unsigned mybit = 1u << lane;
            const int voxbase = off * 4;
            float    vv[4] = { v.x, v.y, v.z, v.w };
            unsigned mm[4] = { m0, m1, m2, m3 };
            int sub = 0;
            #pragma unroll
            for (int c = 0; c < 4; c++) {
                if (mm[c] & mybit) {
                    int p = base + pre + sub;
                    if (p < KCAP) {
                        unsigned int fb  = __float_as_uint(vv[c]);
                        unsigned int vox = (unsigned int)(voxbase + c);
                        // desc by value, tie -> asc voxel index (matches lax.top_k)
                        g_keys[frame * KCAP + p] =
                            ((unsigned long long)fb << 32) | (unsigned int)(~vox);
                    }
                    sub++;
                }
            }
        }
    }

    // ================= Last-block election =================
    __shared__ int isLast;
    __syncthreads();
    if (tid == 0) {
        __threadfence();                               // publish g_keys/g_count writes
        int old = atomicAdd(&g_done[frame], 1);
        isLast = (old == BPF - 1);
    }
    __syncthreads();
    if (!isLast) return;
    __threadfence();                                   // acquire side

    // ================= Phase 2: per-frame NMS (only 1 block per frame) =================
    const float* fin  = in  + (size_t)frame * 2 * VOX;
    float*       fout = out + (size_t)frame * 2 * VOX;

    __shared__ unsigned long long skey[KCAP];
    __shared__ unsigned long long rkey[KCAP];
    __shared__ unsigned int       htab[HASH_SZ];
    __shared__ unsigned short     nbr[KCAP * NBMAX];
    __shared__ unsigned char      nbrcnt[KCAP];
    __shared__ unsigned char      status[KCAP];
    __shared__ int changed;

    int n = __ldcg(&g_count[frame]);
    if (n > KCAP) n = KCAP;

    if (n == 0) {
        // empty frame passes through unchanged (overwrite zeros)
        const float4* s = (const float4*)fin;
        float4*       d = (float4*)fout;
        for (int i = tid; i < 2 * VOX4; i += NT) d[i] = s[i];
        if (tid == 0) { g_count[frame] = 0; g_done[frame] = 0; }
        return;
    }

    for (int i = tid; i < HASH_SZ; i += NT) htab[i] = HEMPTY;
    #pragma unroll
    for (int ii = 0; ii < KCAP / NT; ii++) {
        int i = tid + ii * NT;
        skey[i]   = (i < n) ? __ldcg(&g_keys[frame * KCAP + i]) : 0ULL;
        status[i] = ST_SUPP;
    }
    __syncthreads();
    if (tid == 0) { g_count[frame] = 0; g_done[frame] = 0; }   // reset for next replay

    // ---- rank by counting (keys unique), unrolled x8 for LDS pipelining ----
    {
        const int i0 = tid, i1 = tid + NT;
        unsigned long long k0 = skey[i0];
        unsigned long long k1 = skey[i1];
        int r0 = 0, r1 = 0;
        int j = 0;
        for (; j + 8 <= n; j += 8) {
            unsigned long long kj[8];
            #pragma unroll
            for (int u = 0; u < 8; u++) kj[u] = skey[j + u];
            #pragma unroll
            for (int u = 0; u < 8; u++) { r0 += (kj[u] > k0); r1 += (kj[u] > k1); }
        }
        for (; j < n; j++) {
            unsigned long long kj = skey[j];
            r0 += (kj > k0); r1 += (kj > k1);
        }
        if (i0 < n) {
            rkey[r0] = k0; status[r0] = ST_UNDEC;
            unsigned int vox = ~((unsigned int)k0);
            unsigned int h = (vox * 2654435761u) >> 22;
            unsigned int entry = (vox << 9) | (unsigned int)r0;
            while (atomicCAS(&htab[h], HEMPTY, entry) != HEMPTY) h = (h + 1) & HASH_MASK;
        }
        if (i1 < n) {
            rkey[r1] = k1; status[r1] = ST_UNDEC;
            unsigned int vox = ~((unsigned int)k1);
            unsigned int h = (vox * 2654435761u) >> 22;
            unsigned int entry = (vox << 9) | (unsigned int)r1;
            while (atomicCAS(&htab[h], HEMPTY, entry) != HEMPTY) h = (h + 1) & HASH_MASK;
        }
    }
    __syncthreads();

    // ---- adjacency: earlier-ranked candidates in the 26-neighborhood (dist<2 <=> d2<=3) ----
    for (int r = tid; r < n; r += NT) {
        unsigned int vox = ~((unsigned int)rkey[r]);
        int z = vox >> 10, y = (vox >> 5) & 31, x = vox & 31;
        int cnt = 0; bool ovf = false;
        #pragma unroll
        for (int dz = -1; dz <= 1; dz++)
        #pragma unroll
        for (int dy = -1; dy <= 1; dy++)
        #pragma unroll
        for (int dx = -1; dx <= 1; dx++) {
            if (dz == 0 && dy == 0 && dx == 0) continue;
            int nz = z + dz, ny = y + dy, nx = x + dx;
            if ((unsigned)nz >= 32u || (unsigned)ny >= 32u || (unsigned)nx >= 32u) continue;
            unsigned int nv = ((unsigned)nz << 10) | ((unsigned)ny << 5) | (unsigned)nx;
            unsigned int h = (nv * 2654435761u) >> 22;
            while (true) {
                unsigned int e = htab[h];
                if (e == HEMPTY) break;
                if ((e >> 9) == nv) {
                    int q = (int)(e & 511u);
                    if (q < r) {
                        if (cnt < NBMAX) nbr[r * NBMAX + cnt] = (unsigned short)q;
                        else ovf = true;
                        cnt++;
                    }
                    break;
                }
                h = (h + 1) & HASH_MASK;
            }
        }
        nbrcnt[r] = ovf ? (unsigned char)(NB_OVF | NBMAX) : (unsigned char)cnt;
    }
    __syncthreads();

    // ---- fixpoint NMS (unique fixpoint == sequential greedy) ----
    for (int round = 0; round < KCAP; round++) {
        if (tid == 0) changed = 0;
        __syncthreads();

        for (int r = tid; r < n; r += NT) {
            if (status[r] != ST_UNDEC) continue;
            unsigned char nc = nbrcnt[r];
            bool anyKept = false, allDec = true;
            if (nc & NB_OVF) {
                unsigned int vox = ~((unsigned int)rkey[r]);
                int z = vox >> 10, y = (vox >> 5) & 31, x = vox & 31;
                for (int dz = -1; dz <= 1; dz++)
                for (int dy = -1; dy <= 1; dy++)
                for (int dx = -1; dx <= 1; dx++) {
                    if (dz == 0 && dy == 0 && dx == 0) continue;
                    int nz = z + dz, ny = y + dy, nx = x + dx;
                    if ((unsigned)nz >= 32u || (unsigned)ny >= 32u || (unsigned)nx >= 32u) continue;
                    unsigned int nv = ((unsigned)nz << 10) | ((unsigned)ny << 5) | (unsigned)nx;
                    unsigned int h = (nv * 2654435761u) >> 22;
                    while (true) {
                        unsigned int e = htab[h];
                        if (e == HEMPTY) break;
                        if ((e >> 9) == nv) {
                            int q = (int)(e & 511u);
                            if (q < r) {
                                unsigned char sq = status[q];
                                if (sq == ST_KEPT) anyKept = true;
                                else if (sq == ST_UNDEC) allDec = false;
                            }
                            break;
                        }
                        h = (h + 1) & HASH_MASK;
                    }
                }
            } else {
                #pragma unroll 4
                for (int k = 0; k < (int)nc; k++) {
                    unsigned char sq = status[nbr[r * NBMAX + k]];
                    if (sq == ST_KEPT) anyKept = true;
                    else if (sq == ST_UNDEC) allDec = false;
                }
            }
            if (anyKept)     { status[r] = ST_SUPP; changed = 1; }
            else if (allDec) { status[r] = ST_KEPT; changed = 1; }
        }
        __syncthreads();
        if (changed == 0) break;
        __syncthreads();
    }

    // ---- kept count + MAX_EVENTS rank cut ----
    int c0 = __syncthreads_count(tid      < n && status[tid]      == ST_KEPT);
    int c1 = __syncthreads_count(tid + NT < n && status[tid + NT] == ST_KEPT);
    const bool cut = (c0 + c1 > MAXEV);

    // ---- scatter kept points over pre-zeroed output ----
    for (int r = tid; r < n; r += NT) {
        if (status[r] == ST_KEPT && (!cut || r < MAXEV)) {
            unsigned long long key = rkey[r];
            unsigned int vox = ~((unsigned int)key);
            fout[vox]       = __uint_as_float((unsigned int)(key >> 32));
            fout[VOX + vox] = fin[VOX + vox];
        }
    }
}

extern "C" void kernel_launch(void* const* d_in, const int* in_sizes, int n_in,
                              void* d_out, int out_size)
{
    (void)in_sizes; (void)n_in; (void)out_size;
    const float* x   = (const float*)d_in[0];
    float*       out = (float*)d_out;
    event_filter_fused<<<GRID, NT>>>(x, out);
}

// round 7
// speedup vs baseline: 2.5919x; 2.5919x over previous
#include <cuda_runtime.h>
#include <stdint.h>

#define NFRAMES   256
#define VOX       32768
#define VOX4      (VOX / 4)          // 8192
#define KCAP      512
#define MAXEV     100
#define NT1       256
#define GRID1     2048
#define NT2       512
#define NBUK      4096
#define BUKBASE   (0x3DC00000u >> 13)
#define HASH_SZ   1024
#define HASH_MASK 1023
#define HEMPTY    0xFFFFFFFFu
#define NBMAX     8
#define NB_OVF    0x80

#define ST_UNDEC 0
#define ST_KEPT  1
#define ST_SUPP  2

__device__ unsigned long long g_keys[NFRAMES * KCAP];
__device__ int                g_count[NFRAMES];

// ---------------- Kernel 1: zero output + warp-aggregated compaction ----------------
__global__ __launch_bounds__(NT1)
void zero_compact_kernel(const float* __restrict__ in, float* __restrict__ out)
{
    const float4 z4 = make_float4(0.f, 0.f, 0.f, 0.f);
    const float4* in4 = (const float4*)in;
    float4* out4 = (float4*)out;

    const int total  = NFRAMES * VOX4;           // 2,097,152
    const int stride = GRID1 * NT1;
    const int lane   = threadIdx.x & 31;
    const unsigned FULL = 0xFFFFFFFFu;

    for (int idx = blockIdx.x * NT1 + threadIdx.x; idx < total; idx += stride) {
        const int frame = idx >> 13;
        const int off   = idx & (VOX4 - 1);
        const int base4 = frame << 14;

        out4[base4 + off]        = z4;
        out4[base4 + VOX4 + off] = z4;

        float4 v = in4[base4 + off];
        unsigned m0 = __ballot_sync(FULL, v.x > 0.0f);
        unsigned m1 = __ballot_sync(FULL, v.y > 0.0f);
        unsigned m2 = __ballot_sync(FULL, v.z > 0.0f);
        unsigned m3 = __ballot_sync(FULL, v.w > 0.0f);
        if ((m0 | m1 | m2 | m3) == 0) continue;

        int tot = __popc(m0) + __popc(m1) + __popc(m2) + __popc(m3);
        int base;
        if (lane == 0) base = atomicAdd(&g_count[frame], tot);
        base = __shfl_sync(FULL, base, 0);

        const unsigned lt = (1u << lane) - 1u;
        int pre = __popc(m0 & lt) + __popc(m1 & lt) + __popc(m2 & lt) + __popc(m3 & lt);
        const unsigned mybit = 1u << lane;
        const int voxbase = off * 4;
        float    vv[4] = { v.x, v.y, v.z, v.w };
        unsigned mm[4] = { m0, m1, m2, m3 };
        int sub = 0;
        #pragma unroll
        for (int c = 0; c < 4; c++) {
            if (mm[c] & mybit) {
                int p = base + pre + sub;
                if (p < KCAP) {
                    unsigned int fb  = __float_as_uint(vv[c]);
                    unsigned int vox = (unsigned int)(voxbase + c);
                    // desc by value, tie -> asc voxel index (matches lax.top_k)
                    g_keys[frame * KCAP + p] =
                        ((unsigned long long)fb << 32) | (unsigned int)(~vox);
                }
                sub++;
            }
        }
    }
}

// ---------------- Kernel 2: counting-sort rank (DESCENDING) + adjacency + fixpoint NMS ----------------
__global__ __launch_bounds__(NT2)
void nms_scatter_kernel(const float* __restrict__ in, float* __restrict__ out)
{
    const int frame = blockIdx.x;
    const float* fin  = in  + (size_t)frame * 2 * VOX;
    float*       fout = out + (size_t)frame * 2 * VOX;
    const int tid  = threadIdx.x;
    const int lane = tid & 31;
    const int wid  = tid >> 5;
    const unsigned FULL = 0xFFFFFFFFu;

    __shared__ __align__(16) unsigned char pool[NBUK * 4];   // 16KB: hist -> htab|nbr|bmap
    __shared__ unsigned long long tmp[KCAP];    // bucket-grouped keys
    __shared__ unsigned long long rkey[KCAP];   // rank-ordered keys (descending)
    __shared__ unsigned char      status[KCAP];
    __shared__ unsigned char      nbrcnt[KCAP];
    __shared__ unsigned int       wsum[16], wpre[16];
    __shared__ int changed;

    unsigned int* hist = (unsigned int*)pool;

    int n = g_count[frame];
    if (n > KCAP) n = KCAP;

    if (n == 0) {
        const float4* s = (const float4*)fin;
        float4*       d = (float4*)fout;
        #pragma unroll
        for (int i = tid; i < 2 * VOX4; i += NT2) d[i] = s[i];
        if (tid == 0) g_count[frame] = 0;
        return;
    }
    if (tid == 0) g_count[frame] = 0;            // reset for next graph replay

    const bool valid = (tid < n);
    unsigned long long mykey = valid ? __ldcg(&g_keys[frame * KCAP + tid]) : 0ULL;
    unsigned int myb = 0;
    if (valid) {
        unsigned int fb = (unsigned int)(mykey >> 32);
        int b = (int)(fb >> 13) - (int)BUKBASE;
        b = (b < 0 ? 0 : (b > NBUK - 1 ? NBUK - 1 : b));
        myb = (unsigned int)((NBUK - 1) - b);    // DESCENDING: high energy -> low bucket
    }

    // ---- histogram ----
    #pragma unroll
    for (int ii = 0; ii < NBUK / NT2; ii++) hist[tid + ii * NT2] = 0;
    status[tid] = ST_SUPP;
    __syncthreads();
    if (valid) atomicAdd(&hist[myb], 1u);
    __syncthreads();

    // ---- exclusive scan of hist[0..NBUK), 8 per thread ----
    {
        const int base = tid * (NBUK / NT2);     // 8
        unsigned int tile[NBUK / NT2];
        unsigned int tsum = 0;
        #pragma unroll
        for (int u = 0; u < NBUK / NT2; u++) { tile[u] = hist[base + u]; tsum += tile[u]; }

        unsigned int v = tsum;
        #pragma unroll
        for (int o = 1; o < 32; o <<= 1) {
            unsigned int u = __shfl_up_sync(FULL, v, o);
            if (lane >= o) v += u;
        }
        if (lane == 31) wsum[wid] = v;
        unsigned int wexcl = v - tsum;
        __syncthreads();
        if (wid == 0) {
            unsigned int wv = (lane < 16) ? wsum[lane] : 0u;
            unsigned int iv = wv;
            #pragma unroll
            for (int o = 1; o < 16; o <<= 1) {
                unsigned int u = __shfl_up_sync(FULL, iv, o);
                if (lane >= o) iv += u;
            }
            if (lane < 16) wpre[lane] = iv - wv;
        }
        __syncthreads();
        unsigned int run = wpre[wid] + wexcl;
        #pragma unroll
        for (int u = 0; u < NBUK / NT2; u++) {
            unsigned int c = tile[u];
            hist[base + u] = run;                // exclusive psum
            run += c;
        }
    }
    __syncthreads();

    // ---- placement (hist becomes inclusive bucket ends) ----
    if (valid) {
        unsigned int pos = atomicAdd(&hist[myb], 1u);
        tmp[pos] = mykey;
    }
    __syncthreads();

    // ---- exact descending rank via within-bucket fixup ----
    int myrank = -1;
    if (valid) {
        unsigned int lo = (myb == 0) ? 0u : hist[myb - 1];
        unsigned int hi = hist[myb];
        int r = (int)lo;
        for (unsigned int j = lo; j < hi; j++) r += (tmp[j] > mykey);  // larger key -> earlier
        myrank = r;
        rkey[r] = mykey;
        status[r] = ST_UNDEC;
    }
    __syncthreads();

    // ---- reuse pool: htab (4KB) | nbr (8KB) | bitmap (4KB) ----
    unsigned int*   htab = (unsigned int*)pool;
    unsigned short* nbr  = (unsigned short*)(pool + 4096);
    unsigned int*   bmap = (unsigned int*)(pool + 12288);
    #pragma unroll
    for (int ii = 0; ii < HASH_SZ / NT2; ii++) htab[tid + ii * NT2] = HEMPTY;
    #pragma unroll
    for (int ii = 0; ii < 1024 / NT2; ii++) bmap[tid + ii * NT2] = 0;
    __syncthreads();

    // hash insert (vox -> rank) + occupancy bitmap
    if (valid) {
        unsigned int vox = ~((unsigned int)mykey);
        atomicOr(&bmap[vox >> 5], 1u << (vox & 31));
        unsigned int h = (vox * 2654435761u) >> 22;
        unsigned int entry = (vox << 9) | (unsigned int)myrank;
        while (atomicCAS(&htab[h], HEMPTY, entry) != HEMPTY) h = (h + 1) & HASH_MASK;
    }
    __syncthreads();

    // ---- adjacency: earlier-ranked 26-neighbors (dist<2 <=> d2<=3) ----
    {
        const int r = tid;
        if (r < n) {
            unsigned int vox = ~((unsigned int)rkey[r]);
            int z = vox >> 10, y = (vox >> 5) & 31, x = vox & 31;
            int cnt = 0; bool ovf = false;
            #pragma unroll
            for (int dz = -1; dz <= 1; dz++)
            #pragma unroll
            for (int dy = -1; dy <= 1; dy++)
            #pragma unroll
            for (int dx = -1; dx <= 1; dx++) {
                if (dz == 0 && dy == 0 && dx == 0) continue;
                int nz = z + dz, ny = y + dy, nx = x + dx;
                if ((unsigned)nz >= 32u || (unsigned)ny >= 32u || (unsigned)nx >= 32u) continue;
                unsigned int nv = ((unsigned)nz << 10) | ((unsigned)ny << 5) | (unsigned)nx;
                if (!(bmap[nv >> 5] & (1u << (nv & 31)))) continue;
                unsigned int h = (nv * 2654435761u) >> 22;
                while (true) {
                    unsigned int e = htab[h];
                    if (e == HEMPTY) break;
                    if ((e >> 9) == nv) {
                        int q = (int)(e & 511u);
                        if (q < r) {
                            if (cnt < NBMAX) nbr[r * NBMAX + cnt] = (unsigned short)q;
                            else ovf = true;
                            cnt++;
                        }
                        break;
                    }
                    h = (h + 1) & HASH_MASK;
                }
            }
            nbrcnt[r] = ovf ? (unsigned char)(NB_OVF | NBMAX) : (unsigned char)cnt;
        }
    }
    __syncthreads();

    // ---- fixpoint NMS (unique fixpoint == sequential greedy) ----
    for (int round = 0; round < KCAP; round++) {
        if (tid == 0) changed = 0;
        __syncthreads();

        const int r = tid;
        if (r < n && status[r] == ST_UNDEC) {
            unsigned char nc = nbrcnt[r];
            bool anyKept = false, allDec = true;
            if (nc & NB_OVF) {
                unsigned int vox = ~((unsigned int)rkey[r]);
                int z = vox >> 10, y = (vox >> 5) & 31, x = vox & 31;
                for (int dz = -1; dz <= 1; dz++)
                for (int dy = -1; dy <= 1; dy++)
                for (int dx = -1; dx <= 1; dx++) {
                    if (dz == 0 && dy == 0 && dx == 0) continue;
                    int nz = z + dz, ny = y + dy, nx = x + dx;
                    if ((unsigned)nz >= 32u || (unsigned)ny >= 32u || (unsigned)nx >= 32u) continue;
                    unsigned int nv = ((unsigned)nz << 10) | ((unsigned)ny << 5) | (unsigned)nx;
                    if (!(bmap[nv >> 5] & (1u << (nv & 31)))) continue;
                    unsigned int h = (nv * 2654435761u) >> 22;
                    while (true) {
                        unsigned int e = htab[h];
                        if (e == HEMPTY) break;
                        if ((e >> 9) == nv) {
                            int q = (int)(e & 511u);
                            if (q < r) {
                                unsigned char sq = status[q];
                                if (sq == ST_KEPT) anyKept = true;
                                else if (sq == ST_UNDEC) allDec = false;
                            }
                            break;
                        }
                        h = (h + 1) & HASH_MASK;
                    }
                }
            } else {
                #pragma unroll 4
                for (int k = 0; k < (int)nc; k++) {
                    unsigned char sq = status[nbr[r * NBMAX + k]];
                    if (sq == ST_KEPT) anyKept = true;
                    else if (sq == ST_UNDEC) allDec = false;
                }
            }
            if (anyKept)     { status[r] = ST_SUPP; changed = 1; }
            else if (allDec) { status[r] = ST_KEPT; changed = 1; }
        }
        __syncthreads();
        if (changed == 0) break;
        __syncthreads();
    }

    // ---- kept count + MAX_EVENTS rank cut ----
    int kept = __syncthreads_count(tid < n && status[tid] == ST_KEPT);
    const bool cut = (kept > MAXEV);

    // ---- scatter kept points over pre-zeroed output ----
    {
        const int r = tid;
        if (r < n && status[r] == ST_KEPT && (!cut || r < MAXEV)) {
            unsigned long long key = rkey[r];
            unsigned int vox = ~((unsigned int)key);
            fout[vox]       = __uint_as_float((unsigned int)(key >> 32));
            fout[VOX + vox] = fin[VOX + vox];
        }
    }
}

extern "C" void kernel_launch(void* const* d_in, const int* in_sizes, int n_in,
                              void* d_out, int out_size)
{
    (void)in_sizes; (void)n_in; (void)out_size;
    const float* x   = (const float*)d_in[0];
    float*       out = (float*)d_out;
    zero_compact_kernel<<<GRID1, NT1>>>(x, out);
    nms_scatter_kernel<<<NFRAMES, NT2>>>(x, out);
}

// round 8
// speedup vs baseline: 3.4956x; 1.3487x over previous
#include <cuda_runtime.h>
#include <stdint.h>

#define NFRAMES   256
#define VOX       32768
#define VOX4      (VOX / 4)          // 8192 float4 per channel per frame
#define KCAP      512
#define MAXEV     100
#define NT        512
#define SPT       (VOX4 / NT)        // 16 float4 slots per thread
#define NBUK      4096
#define BUKBASE   (0x3DC00000u >> 13)
#define HASH_SZ   1024
#define HASH_MASK 1023
#define HEMPTY    0xFFFFFFFFu
#define NBMAX     8
#define NB_OVF    0x80

#define ST_UNDEC 0
#define ST_KEPT  1
#define ST_SUPP  2

__global__ __launch_bounds__(NT)
void event_filter_kernel(const float* __restrict__ in, float* __restrict__ out)
{
    const int frame = blockIdx.x;
    const int tid   = threadIdx.x;
    const int lane  = tid & 31;
    const int wid   = tid >> 5;
    const unsigned FULL = 0xFFFFFFFFu;

    const float4* in4  = (const float4*)in;
    float4*       out4 = (float4*)out;
    const int base4 = frame << 14;               // frame start in float4 units (2*VOX4)
    const float* fin  = in  + (size_t)frame * 2 * VOX;
    float*       fout = out + (size_t)frame * 2 * VOX;

    __shared__ __align__(16) unsigned char pool[NBUK * 4];  // 16KB: hist -> htab|nbr|bmap
    __shared__ unsigned long long tmp[KCAP];     // bucket-grouped keys
    __shared__ unsigned long long rkey[KCAP];    // compact buffer, then rank-ordered keys
    __shared__ unsigned char      status[KCAP];
    __shared__ unsigned char      nbrcnt[KCAP];
    __shared__ unsigned int       wsum[16], wpre[16];
    __shared__ int cnt_sh;
    __shared__ int changed;

    unsigned int* hist = (unsigned int*)pool;

    // init (pool not used until histogram; rkey filled by compaction)
    if (tid == 0) cnt_sh = 0;
    #pragma unroll
    for (int ii = 0; ii < NBUK / NT; ii++) hist[tid + ii * NT] = 0;
    status[tid] = ST_SUPP;
    __syncthreads();

    // ================= Phase 1: zero output + read energy + compact to smem =================
    {
        const float4 z4 = make_float4(0.f, 0.f, 0.f, 0.f);
        #pragma unroll
        for (int k = 0; k < SPT; k++) {
            const int off = tid + k * NT;
            out4[base4 + off]        = z4;
            out4[base4 + VOX4 + off] = z4;

            float4 v = in4[base4 + off];
            unsigned m0 = __ballot_sync(FULL, v.x > 0.0f);
            unsigned m1 = __ballot_sync(FULL, v.y > 0.0f);
            unsigned m2 = __ballot_sync(FULL, v.z > 0.0f);
            unsigned m3 = __ballot_sync(FULL, v.w > 0.0f);
            if ((m0 | m1 | m2 | m3) == 0) continue;

            int tot = __popc(m0) + __popc(m1) + __popc(m2) + __popc(m3);
            int base;
            if (lane == 0) base = atomicAdd(&cnt_sh, tot);
            base = __shfl_sync(FULL, base, 0);

            const unsigned lt = (1u << lane) - 1u;
            int pre = __popc(m0 & lt) + __popc(m1 & lt) + __popc(m2 & lt) + __popc(m3 & lt);
            const unsigned mybit = 1u << lane;
            const int voxbase = off * 4;
            float    vv[4] = { v.x, v.y, v.z, v.w };
            unsigned mm[4] = { m0, m1, m2, m3 };
            int sub = 0;
            #pragma unroll
            for (int c = 0; c < 4; c++) {
                if (mm[c] & mybit) {
                    int p = base + pre + sub;
                    if (p < KCAP) {
                        unsigned int fb  = __float_as_uint(vv[c]);
                        unsigned int vox = (unsigned int)(voxbase + c);
                        // desc by value, tie -> asc voxel index (matches lax.top_k)
                        rkey[p] = ((unsigned long long)fb << 32) | (unsigned int)(~vox);
                    }
                    sub++;
                }
            }
        }
    }
    __syncthreads();

    int n = cnt_sh;
    if (n > KCAP) n = KCAP;

    if (n == 0) {
        // empty frame passes through unchanged (overwrite the zeros; barrier above orders)
        const float4* s = (const float4*)fin;
        float4*       d = (float4*)fout;
        #pragma unroll
        for (int i = tid; i < 2 * VOX4; i += NT) d[i] = s[i];
        return;
    }

    // ================= Phase 2: counting-sort rank (descending) =================
    const bool valid = (tid < n);
    unsigned long long mykey = valid ? rkey[tid] : 0ULL;   // read before rkey is overwritten
    unsigned int myb = 0;
    if (valid) {
        unsigned int fb = (unsigned int)(mykey >> 32);
        int b = (int)(fb >> 13) - (int)BUKBASE;
        b = (b < 0 ? 0 : (b > NBUK - 1 ? NBUK - 1 : b));
        myb = (unsigned int)((NBUK - 1) - b);    // high energy -> low bucket -> low rank
    }
    if (valid) atomicAdd(&hist[myb], 1u);
    __syncthreads();

    // exclusive scan of hist[0..NBUK), 8 buckets per thread
    {
        const int base = tid * (NBUK / NT);      // 8
        unsigned int tile[NBUK / NT];
        unsigned int tsum = 0;
        #pragma unroll
        for (int u = 0; u < NBUK / NT; u++) { tile[u] = hist[base + u]; tsum += tile[u]; }

        unsigned int v = tsum;
        #pragma unroll
        for (int o = 1; o < 32; o <<= 1) {
            unsigned int u = __shfl_up_sync(FULL, v, o);
            if (lane >= o) v += u;
        }
        if (lane == 31) wsum[wid] = v;
        unsigned int wexcl = v - tsum;
        __syncthreads();
        if (wid == 0) {
            unsigned int wv = (lane < 16) ? wsum[lane] : 0u;
            unsigned int iv = wv;
            #pragma unroll
            for (int o = 1; o < 16; o <<= 1) {
                unsigned int u = __shfl_up_sync(FULL, iv, o);
                if (lane >= o) iv += u;
            }
            if (lane < 16) wpre[lane] = iv - wv;
        }
        __syncthreads();
        unsigned int run = wpre[wid] + wexcl;
        #pragma unroll
        for (int u = 0; u < NBUK / NT; u++) {
            unsigned int c = tile[u];
            hist[base + u] = run;                // exclusive psum
            run += c;
        }
    }
    __syncthreads();

    // placement (hist becomes inclusive bucket ends)
    if (valid) {
        unsigned int pos = atomicAdd(&hist[myb], 1u);
        tmp[pos] = mykey;
    }
    __syncthreads();

    // exact descending rank via within-bucket fixup (range = [hist[b-1], hist[b]))
    int myrank = -1;
    if (valid) {
        unsigned int lo = (myb == 0) ? 0u : hist[myb - 1];
        unsigned int hi = hist[myb];
        int r = (int)lo;
        for (unsigned int j = lo; j < hi; j++) r += (tmp[j] > mykey);
        myrank = r;
        rkey[r] = mykey;
        status[r] = ST_UNDEC;
    }
    __syncthreads();

    // ================= Phase 3: reuse pool: htab (4KB) | nbr (8KB) | bitmap (4KB) =================
    unsigned int*   htab = (unsigned int*)pool;
    unsigned short* nbr  = (unsigned short*)(pool + 4096);
    unsigned int*   bmap = (unsigned int*)(pool + 12288);
    #pragma unroll
    for (int ii = 0; ii < HASH_SZ / NT; ii++) htab[tid + ii * NT] = HEMPTY;
    #pragma unroll
    for (int ii = 0; ii < 1024 / NT; ii++) bmap[tid + ii * NT] = 0;
    __syncthreads();

    if (valid) {
        unsigned int vox = ~((unsigned int)mykey);
        atomicOr(&bmap[vox >> 5], 1u << (vox & 31));
        unsigned int h = (vox * 2654435761u) >> 22;
        unsigned int entry = (vox << 9) | (unsigned int)myrank;
        while (atomicCAS(&htab[h], HEMPTY, entry) != HEMPTY) h = (h + 1) & HASH_MASK;
    }
    __syncthreads();

    // adjacency: earlier-ranked 26-neighbors (dist<2 on int coords <=> d2<=3)
    {
        const int r = tid;
        if (r < n) {
            unsigned int vox = ~((unsigned int)rkey[r]);
            int z = vox >> 10, y = (vox >> 5) & 31, x = vox & 31;
            int cnt = 0; bool ovf = false;
            #pragma unroll
            for (int dz = -1; dz <= 1; dz++)
            #pragma unroll
            for (int dy = -1; dy <= 1; dy++)
            #pragma unroll
            for (int dx = -1; dx <= 1; dx++) {
                if (dz == 0 && dy == 0 && dx == 0) continue;
                int nz = z + dz, ny = y + dy, nx = x + dx;
                if ((unsigned)nz >= 32u || (unsigned)ny >= 32u || (unsigned)nx >= 32u) continue;
                unsigned int nv = ((unsigned)nz << 10) | ((unsigned)ny << 5) | (unsigned)nx;
                if (!(bmap[nv >> 5] & (1u << (nv & 31)))) continue;
                unsigned int h = (nv * 2654435761u) >> 22;
                while (true) {
                    unsigned int e = htab[h];
                    if (e == HEMPTY) break;
                    if ((e >> 9) == nv) {
                        int q = (int)(e & 511u);
                        if (q < r) {
                            if (cnt < NBMAX) nbr[r * NBMAX + cnt] = (unsigned short)q;
                            else ovf = true;
                            cnt++;
                        }
                        break;
                    }
                    h = (h + 1) & HASH_MASK;
                }
            }
            nbrcnt[r] = ovf ? (unsigned char)(NB_OVF | NBMAX) : (unsigned char)cnt;
        }
    }
    __syncthreads();

    // ================= Phase 4: fixpoint NMS (unique fixpoint == sequential greedy) =================
    for (int round = 0; round < KCAP; round++) {
        if (tid == 0) changed = 0;
        __syncthreads();

        const int r = tid;
        if (r < n && status[r] == ST_UNDEC) {
            unsigned char nc = nbrcnt[r];
            bool anyKept = false, allDec = true;
            if (nc & NB_OVF) {
                unsigned int vox = ~((unsigned int)rkey[r]);
                int z = vox >> 10, y = (vox >> 5) & 31, x = vox & 31;
                for (int dz = -1; dz <= 1; dz++)
                for (int dy = -1; dy <= 1; dy++)
                for (int dx = -1; dx <= 1; dx++) {
                    if (dz == 0 && dy == 0 && dx == 0) continue;
                    int nz = z + dz, ny = y + dy, nx = x + dx;
                    if ((unsigned)nz >= 32u || (unsigned)ny >= 32u || (unsigned)nx >= 32u) continue;
                    unsigned int nv = ((unsigned)nz << 10) | ((unsigned)ny << 5) | (unsigned)nx;
                    if (!(bmap[nv >> 5] & (1u << (nv & 31)))) continue;
                    unsigned int h = (nv * 2654435761u) >> 22;
                    while (true) {
                        unsigned int e = htab[h];
                        if (e == HEMPTY) break;
                        if ((e >> 9) == nv) {
                            int q = (int)(e & 511u);
                            if (q < r) {
                                unsigned char sq = status[q];
                                if (sq == ST_KEPT) anyKept = true;
                                else if (sq == ST_UNDEC) allDec = false;
                            }
                            break;
                        }
                        h = (h + 1) & HASH_MASK;
                    }
                }
            } else {
                #pragma unroll 4
                for (int k = 0; k < (int)nc; k++) {
                    unsigned char sq = status[nbr[r * NBMAX + k]];
                    if (sq == ST_KEPT) anyKept = true;
                    else if (sq == ST_UNDEC) allDec = false;
                }
            }
            if (anyKept)     { status[r] = ST_SUPP; changed = 1; }
            else if (allDec) { status[r] = ST_KEPT; changed = 1; }
        }
        __syncthreads();
        if (changed == 0) break;
        __syncthreads();
    }

    // ================= Phase 5: kept count + MAX_EVENTS rank cut + scatter =================
    int kept = __syncthreads_count(tid < n && status[tid] == ST_KEPT);
    const bool cut = (kept > MAXEV);

    {
        const int r = tid;
        if (r < n && status[r] == ST_KEPT && (!cut || r < MAXEV)) {
            unsigned long long key = rkey[r];
            unsigned int vox = ~((unsigned int)key);
            fout[vox]       = __uint_as_float((unsigned int)(key >> 32));
            fout[VOX + vox] = fin[VOX + vox];
        }
    }
}

extern "C" void kernel_launch(void* const* d_in, const int* in_sizes, int n_in,
                              void* d_out, int out_size)
{
    (void)in_sizes; (void)n_in; (void)out_size;
    const float* x   = (const float*)d_in[0];
    float*       out = (float*)d_out;
    event_filter_kernel<<<NFRAMES, NT>>>(x, out);
}

// round 9
// speedup vs baseline: 4.0715x; 1.1648x over previous
#include <cuda_runtime.h>
#include <stdint.h>

#define NFRAMES   256
#define VOX       32768
#define VOX4      (VOX / 4)          // 8192 float4 per channel per frame
#define KCAP      512
#define MAXEV     100
#define NT        1024
#define SPT       (VOX4 / NT)        // 8 float4 slots per thread
#define NBUK      4096
#define BUKBASE   (0x3DC00000u >> 13)
#define HASH_SZ   1024
#define HASH_MASK 1023
#define HEMPTY    0xFFFFFFFFu
#define NBMAX     8
#define NB_OVF    0x80

#define ST_UNDEC 0
#define ST_KEPT  1
#define ST_SUPP  2

__global__ __launch_bounds__(NT, 2)
void event_filter_kernel(const float* __restrict__ in, float* __restrict__ out)
{
    const int frame = blockIdx.x;
    const int tid   = threadIdx.x;
    const int lane  = tid & 31;
    const int wid   = tid >> 5;
    const unsigned FULL = 0xFFFFFFFFu;

    const float4* in4  = (const float4*)in;
    float4*       out4 = (float4*)out;
    const int base4 = frame << 14;               // frame start in float4 units (2*VOX4)
    const float* fin  = in  + (size_t)frame * 2 * VOX;
    float*       fout = out + (size_t)frame * 2 * VOX;

    __shared__ __align__(16) unsigned char pool[NBUK * 4];  // 16KB: hist -> htab|nbr|bmap
    __shared__ unsigned long long tmp[KCAP];     // bucket-grouped keys
    __shared__ unsigned long long rkey[KCAP];    // compact buffer, then rank-ordered keys
    __shared__ unsigned char      status[KCAP];
    __shared__ unsigned char      nbrcnt[KCAP];
    __shared__ unsigned int       wsum[32], wpre[32];
    __shared__ int cnt_sh;
    __shared__ int changed;

    unsigned int* hist = (unsigned int*)pool;

    if (tid == 0) cnt_sh = 0;
    #pragma unroll
    for (int ii = 0; ii < NBUK / NT; ii++) hist[tid + ii * NT] = 0;
    if (tid < KCAP) status[tid] = ST_SUPP;
    __syncthreads();

    // ================= Phase 1: zero output + read energy + compact to smem =================
    {
        const float4 z4 = make_float4(0.f, 0.f, 0.f, 0.f);
        #pragma unroll
        for (int k = 0; k < SPT; k++) {
            const int off = tid + k * NT;
            out4[base4 + off]        = z4;
            out4[base4 + VOX4 + off] = z4;

            float4 v = in4[base4 + off];
            unsigned m0 = __ballot_sync(FULL, v.x > 0.0f);
            unsigned m1 = __ballot_sync(FULL, v.y > 0.0f);
            unsigned m2 = __ballot_sync(FULL, v.z > 0.0f);
            unsigned m3 = __ballot_sync(FULL, v.w > 0.0f);
            if ((m0 | m1 | m2 | m3) == 0) continue;

            int tot = __popc(m0) + __popc(m1) + __popc(m2) + __popc(m3);
            int base;
            if (lane == 0) base = atomicAdd(&cnt_sh, tot);
            base = __shfl_sync(FULL, base, 0);

            const unsigned lt = (1u << lane) - 1u;
            int pre = __popc(m0 & lt) + __popc(m1 & lt) + __popc(m2 & lt) + __popc(m3 & lt);
            const unsigned mybit = 1u << lane;
            const int voxbase = off * 4;
            float    vv[4] = { v.x, v.y, v.z, v.w };
            unsigned mm[4] = { m0, m1, m2, m3 };
            int sub = 0;
            #pragma unroll
            for (int c = 0; c < 4; c++) {
                if (mm[c] & mybit) {
                    int p = base + pre + sub;
                    if (p < KCAP) {
                        unsigned int fb  = __float_as_uint(vv[c]);
                        unsigned int vox = (unsigned int)(voxbase + c);
                        // desc by value, tie -> asc voxel index (matches lax.top_k)
                        rkey[p] = ((unsigned long long)fb << 32) | (unsigned int)(~vox);
                    }
                    sub++;
                }
            }
        }
    }
    __syncthreads();

    int n = cnt_sh;
    if (n > KCAP) n = KCAP;

    if (n == 0) {
        // empty frame passes through unchanged (overwrite the zeros)
        const float4* s = (const float4*)fin;
        float4*       d = (float4*)fout;
        #pragma unroll
        for (int i = tid; i < 2 * VOX4; i += NT) d[i] = s[i];
        return;
    }

    // ================= Phase 2: counting-sort rank (descending) =================
    const bool valid = (tid < n);
    unsigned long long mykey = valid ? rkey[tid] : 0ULL;   // read before rkey is overwritten
    unsigned int myb = 0;
    if (valid) {
        unsigned int fb = (unsigned int)(mykey >> 32);
        int b = (int)(fb >> 13) - (int)BUKBASE;
        b = (b < 0 ? 0 : (b > NBUK - 1 ? NBUK - 1 : b));
        myb = (unsigned int)((NBUK - 1) - b);    // high energy -> low bucket -> low rank
    }
    if (valid) atomicAdd(&hist[myb], 1u);
    __syncthreads();

    // exclusive scan of hist[0..NBUK), 4 buckets per thread, 32 warps
    {
        const int base = tid * (NBUK / NT);      // 4
        unsigned int tile[NBUK / NT];
        unsigned int tsum = 0;
        #pragma unroll
        for (int u = 0; u < NBUK / NT; u++) { tile[u] = hist[base + u]; tsum += tile[u]; }

        unsigned int v = tsum;
        #pragma unroll
        for (int o = 1; o < 32; o <<= 1) {
            unsigned int u = __shfl_up_sync(FULL, v, o);
            if (lane >= o) v += u;
        }
        if (lane == 31) wsum[wid] = v;
        unsigned int wexcl = v - tsum;
        __syncthreads();
        if (wid == 0) {
            unsigned int wv = wsum[lane];
            unsigned int iv = wv;
            #pragma unroll
            for (int o = 1; o < 32; o <<= 1) {
                unsigned int u = __shfl_up_sync(FULL, iv, o);
                if (lane >= o) iv += u;
            }
            wpre[lane] = iv - wv;
        }
        __syncthreads();
        unsigned int run = wpre[wid] + wexcl;
        #pragma unroll
        for (int u = 0; u < NBUK / NT; u++) {
            unsigned int c = tile[u];
            hist[base + u] = run;                // exclusive psum
            run += c;
        }
    }
    __syncthreads();

    // placement (hist becomes inclusive bucket ends)
    if (valid) {
        unsigned int pos = atomicAdd(&hist[myb], 1u);
        tmp[pos] = mykey;
    }
    __syncthreads();

    // exact descending rank via within-bucket fixup (range = [hist[b-1], hist[b]))
    int myrank = -1;
    if (valid) {
        unsigned int lo = (myb == 0) ? 0u : hist[myb - 1];
        unsigned int hi = hist[myb];
        int r = (int)lo;
        for (unsigned int j = lo; j < hi; j++) r += (tmp[j] > mykey);
        myrank = r;
        rkey[r] = mykey;
        status[r] = ST_UNDEC;
    }
    __syncthreads();

    // ================= Phase 3: reuse pool: htab (4KB) | nbr (8KB) | bitmap (4KB) =================
    unsigned int*   htab = (unsigned int*)pool;
    unsigned short* nbr  = (unsigned short*)(pool + 4096);
    unsigned int*   bmap = (unsigned int*)(pool + 12288);
    if (tid < HASH_SZ) htab[tid] = HEMPTY;
    if (tid < 1024)    bmap[tid] = 0;
    __syncthreads();

    if (valid) {
        unsigned int vox = ~((unsigned int)mykey);
        atomicOr(&bmap[vox >> 5], 1u << (vox & 31));
        unsigned int h = (vox * 2654435761u) >> 22;
        unsigned int entry = (vox << 9) | (unsigned int)myrank;
        while (atomicCAS(&htab[h], HEMPTY, entry) != HEMPTY) h = (h + 1) & HASH_MASK;
    }
    __syncthreads();

    // adjacency: earlier-ranked 26-neighbors (dist<2 on int coords <=> d2<=3)
    {
        const int r = tid;
        if (r < n) {
            unsigned int vox = ~((unsigned int)rkey[r]);
            int z = vox >> 10, y = (vox >> 5) & 31, x = vox & 31;
            int cnt = 0; bool ovf = false;
            #pragma unroll
            for (int dz = -1; dz <= 1; dz++)
            #pragma unroll
            for (int dy = -1; dy <= 1; dy++)
            #pragma unroll
            for (int dx = -1; dx <= 1; dx++) {
                if (dz == 0 && dy == 0 && dx == 0) continue;
                int nz = z + dz, ny = y + dy, nx = x + dx;
                if ((unsigned)nz >= 32u || (unsigned)ny >= 32u || (unsigned)nx >= 32u) continue;
                unsigned int nv = ((unsigned)nz << 10) | ((unsigned)ny << 5) | (unsigned)nx;
                if (!(bmap[nv >> 5] & (1u << (nv & 31)))) continue;
                unsigned int h = (nv * 2654435761u) >> 22;
                while (true) {
                    unsigned int e = htab[h];
                    if (e == HEMPTY) break;
                    if ((e >> 9) == nv) {
                        int q = (int)(e & 511u);
                        if (q < r) {
                            if (cnt < NBMAX) nbr[r * NBMAX + cnt] = (unsigned short)q;
                            else ovf = true;
                            cnt++;
                        }
                        break;
                    }
                    h = (h + 1) & HASH_MASK;
                }
            }
            nbrcnt[r] = ovf ? (unsigned char)(NB_OVF | NBMAX) : (unsigned char)cnt;
        }
    }
    __syncthreads();

    // ================= Phase 4: fixpoint NMS (unique fixpoint == sequential greedy) =================
    for (int round = 0; round < KCAP; round++) {
        if (tid == 0) changed = 0;
        __syncthreads();

        const int r = tid;
        if (r < n && status[r] == ST_UNDEC) {
            unsigned char nc = nbrcnt[r];
            bool anyKept = false, allDec = true;
            if (nc & NB_OVF) {
                unsigned int vox = ~((unsigned int)rkey[r]);
                int z = vox >> 10, y = (vox >> 5) & 31, x = vox & 31;
                for (int dz = -1; dz <= 1; dz++)
                for (int dy = -1; dy <= 1; dy++)
                for (int dx = -1; dx <= 1; dx++) {
                    if (dz == 0 && dy == 0 && dx == 0) continue;
                    int nz = z + dz, ny = y + dy, nx = x + dx;
                    if ((unsigned)nz >= 32u || (unsigned)ny >= 32u || (unsigned)nx >= 32u) continue;
                    unsigned int nv = ((unsigned)nz << 10) | ((unsigned)ny << 5) | (unsigned)nx;
                    if (!(bmap[nv >> 5] & (1u << (nv & 31)))) continue;
                    unsigned int h = (nv * 2654435761u) >> 22;
                    while (true) {
                        unsigned int e = htab[h];
                        if (e == HEMPTY) break;
                        if ((e >> 9) == nv) {
                            int q = (int)(e & 511u);
                            if (q < r) {
                                unsigned char sq = status[q];
                                if (sq == ST_KEPT) anyKept = true;
                                else if (sq == ST_UNDEC) allDec = false;
                            }
                            break;
                        }
                        h = (h + 1) & HASH_MASK;
                    }
                }
            } else {
                #pragma unroll 4
                for (int k = 0; k < (int)nc; k++) {
                    unsigned char sq = status[nbr[r * NBMAX + k]];
                    if (sq == ST_KEPT) anyKept = true;
                    else if (sq == ST_UNDEC) allDec = false;
                }
            }
            if (anyKept)     { status[r] = ST_SUPP; changed = 1; }
            else if (allDec) { status[r] = ST_KEPT; changed = 1; }
        }
        __syncthreads();
        if (changed == 0) break;
        __syncthreads();
    }

    // ================= Phase 5: kept count + MAX_EVENTS rank cut + scatter =================
    int kept = __syncthreads_count(tid < n && status[tid] == ST_KEPT);
    const bool cut = (kept > MAXEV);

    {
        const int r = tid;
        if (r < n && status[r] == ST_KEPT && (!cut || r < MAXEV)) {
            unsigned long long key = rkey[r];
            unsigned int vox = ~((unsigned int)key);
            fout[vox]       = __uint_as_float((unsigned int)(key >> 32));
            fout[VOX + vox] = fin[VOX + vox];
        }
    }
}

extern "C" void kernel_launch(void* const* d_in, const int* in_sizes, int n_in,
                              void* d_out, int out_size)
{
    (void)in_sizes; (void)n_in; (void)out_size;
    const float* x   = (const float*)d_in[0];
    float*       out = (float*)d_out;
    event_filter_kernel<<<NFRAMES, NT>>>(x, out);
}